// round 16
// baseline (speedup 1.0000x reference)
#include <cuda_runtime.h>

// ---------------- problem constants ----------------
#define HID        300
#define N_ATOMS_C  100000
#define N_BONDS_C  200000
#define NA1        (N_ATOMS_C + 1)
#define NB1        (N_BONDS_C + 1)
#define N_MOLS_C   5000
#define APM        20

// ---------------- scratch (static __device__, allocation-free) ----------------
__device__ float g_inp[NB1 * HID];
__device__ float g_msg[NB1 * HID];
__device__ float g_M[NB1 * HID];
__device__ float g_aw[NA1 * HID];
__device__ float g_hidden[NA1 * HID];
// transposed, zero-padded, tf32-rounded weights: Wt[n][k], n<320, k<kpad
__device__ float g_WtI[320 * 160];   // W_i: K=147 -> kpad 160
__device__ float g_WtH[320 * 320];   // W_h: K=300 -> kpad 320
__device__ float g_WtO[320 * 448];   // W_o: K=433 -> kpad 448

// ---------------- helpers ----------------
__device__ __forceinline__ unsigned tf32c(float x) {
    unsigned r;
    asm("cvt.rna.tf32.f32 %0, %1;" : "=r"(r) : "f"(x));
    return r;
}
__device__ __forceinline__ void mma8(float d[4], uint4 a, uint2 b) {
    asm volatile(
        "mma.sync.aligned.m16n8k8.row.col.f32.tf32.tf32.f32 "
        "{%0,%1,%2,%3}, {%4,%5,%6,%7}, {%8,%9}, {%0,%1,%2,%3};"
        : "+f"(d[0]), "+f"(d[1]), "+f"(d[2]), "+f"(d[3])
        : "r"(a.x), "r"(a.y), "r"(a.z), "r"(a.w), "r"(b.x), "r"(b.y));
}

// A element loader: mode 0 = plain row-major [M x K]; mode 2 = concat [f_atoms(133)|aw(300)]
__device__ __forceinline__ float loadA(const float* __restrict__ A,
                                       const float* __restrict__ A2,
                                       int r, int c, int M, int K, int mode) {
    if (r >= M) return 0.f;
    if (mode == 0) return (c < K) ? A[(size_t)r * K + c] : 0.f;
    if (c < 133)   return A[(size_t)r * 133 + c];
    if (c < 433)   return A2[(size_t)r * 300 + (c - 133)];
    return 0.f;
}

// ---------------- mma.sync tf32 GEMM ----------------
// C[M x 300] = act(A[M x K] @ Wt^T + bias); Wt is [320 x kpad] n-major, tf32-rounded, zero-padded.
// CTA: 128 rows x 160 cols (blockIdx.y in {0,1}); BK=32; 8 warps = 4(m) x 2(n); warp = 32x80.
// SMEM is fragment-major: A frag quad at Ab[s*1024 + m16tile*128 + lane*4] (LDS.128);
// B frag pair at Bb[s*1280 + n8tile*64 + lane*2] (LDS.64). Staging STS is contiguous per warp.
#define ABUF_FL   4096
#define BBUF_FL   5120
#define STAGE_FL  (ABUF_FL + BBUF_FL)         // 9216 floats
#define SMEM_B    (2 * STAGE_FL * 4)          // 73728 bytes

__global__ __launch_bounds__(256, 1)
void gemm_mma(const float* __restrict__ A, const float* __restrict__ A2,
              const float* __restrict__ Bt, const float* __restrict__ bias,
              float* __restrict__ C, int M, int K, int kpad, int mode, int relu)
{
    extern __shared__ float sm[];
    const int tid  = threadIdx.x;
    const int warp = tid >> 5, lane = tid & 31;
    const int g    = lane >> 2, t = lane & 3;
    const int wm   = warp & 3,  wn = warp >> 2;
    const int bm   = blockIdx.x * 128;
    const int nb0  = blockIdx.y * 160;
    const int nCh  = kpad >> 5;

    float acc[2][10][4];
#pragma unroll
    for (int mt = 0; mt < 2; mt++)
#pragma unroll
        for (int nt = 0; nt < 10; nt++)
#pragma unroll
            for (int j = 0; j < 4; j++) acc[mt][nt][j] = 0.f;

    const int r0 = bm + warp * 16 + g;   // staging: warp w owns m16-tile w
    uint4 pa[4];
    uint2 pb[10];

    // ---- prologue: stage chunk 0 ----
    {
#pragma unroll
        for (int s = 0; s < 4; s++) {
            int c0 = s * 8 + t;
            pa[s].x = tf32c(loadA(A, A2, r0,     c0,     M, K, mode));
            pa[s].y = tf32c(loadA(A, A2, r0 + 8, c0,     M, K, mode));
            pa[s].z = tf32c(loadA(A, A2, r0,     c0 + 4, M, K, mode));
            pa[s].w = tf32c(loadA(A, A2, r0 + 8, c0 + 4, M, K, mode));
        }
#pragma unroll
        for (int i = 0; i < 10; i++) {
            int ts = warp * 10 + i, nt = ts >> 2, sl = ts & 3;
            const float* bp = Bt + (size_t)(nb0 + nt * 8 + g) * kpad + sl * 8 + t;
            pb[i].x = __float_as_uint(bp[0]);
            pb[i].y = __float_as_uint(bp[4]);
        }
        float* Ab = sm;
        float* Bb = sm + ABUF_FL;
#pragma unroll
        for (int s = 0; s < 4; s++)
            *reinterpret_cast<uint4*>(Ab + s * 1024 + warp * 128 + lane * 4) = pa[s];
#pragma unroll
        for (int i = 0; i < 10; i++) {
            int ts = warp * 10 + i, nt = ts >> 2, sl = ts & 3;
            *reinterpret_cast<uint2*>(Bb + sl * 1280 + nt * 64 + lane * 2) = pb[i];
        }
    }
    __syncthreads();

    // ---- mainloop ----
    for (int ch = 0; ch < nCh; ch++) {
        const bool more = (ch + 1) < nCh;
        if (more) {
            const int k0 = (ch + 1) << 5;
#pragma unroll
            for (int s = 0; s < 4; s++) {
                int c0 = k0 + s * 8 + t;
                pa[s].x = tf32c(loadA(A, A2, r0,     c0,     M, K, mode));
                pa[s].y = tf32c(loadA(A, A2, r0 + 8, c0,     M, K, mode));
                pa[s].z = tf32c(loadA(A, A2, r0,     c0 + 4, M, K, mode));
                pa[s].w = tf32c(loadA(A, A2, r0 + 8, c0 + 4, M, K, mode));
            }
#pragma unroll
            for (int i = 0; i < 10; i++) {
                int ts = warp * 10 + i, nt = ts >> 2, sl = ts & 3;
                const float* bp = Bt + (size_t)(nb0 + nt * 8 + g) * kpad + k0 + sl * 8 + t;
                pb[i].x = __float_as_uint(bp[0]);
                pb[i].y = __float_as_uint(bp[4]);
            }
        }

        // compute current buffer
        {
            const float* Ab = sm + (ch & 1) * STAGE_FL;
            const float* Bb = Ab + ABUF_FL;
#pragma unroll
            for (int s = 0; s < 4; s++) {
                uint4 af[2];
                uint2 bf[10];
#pragma unroll
                for (int mt = 0; mt < 2; mt++)
                    af[mt] = *reinterpret_cast<const uint4*>(
                        Ab + s * 1024 + (wm * 2 + mt) * 128 + lane * 4);
#pragma unroll
                for (int nt = 0; nt < 10; nt++)
                    bf[nt] = *reinterpret_cast<const uint2*>(
                        Bb + s * 1280 + (wn * 10 + nt) * 64 + lane * 2);
#pragma unroll
                for (int mt = 0; mt < 2; mt++)
#pragma unroll
                    for (int nt = 0; nt < 10; nt++)
                        mma8(acc[mt][nt], af[mt], bf[nt]);
            }
        }

        if (more) {
            float* Ab = sm + ((ch + 1) & 1) * STAGE_FL;
            float* Bb = Ab + ABUF_FL;
#pragma unroll
            for (int s = 0; s < 4; s++)
                *reinterpret_cast<uint4*>(Ab + s * 1024 + warp * 128 + lane * 4) = pa[s];
#pragma unroll
            for (int i = 0; i < 10; i++) {
                int ts = warp * 10 + i, nt = ts >> 2, sl = ts & 3;
                *reinterpret_cast<uint2*>(Bb + sl * 1280 + nt * 64 + lane * 2) = pb[i];
            }
        }
        __syncthreads();
    }

    // ---- epilogue: c0,c1 = (row g, cols 2t,2t+1); c2,c3 = (row g+8, same cols) ----
#pragma unroll
    for (int mt = 0; mt < 2; mt++) {
        int rb = bm + wm * 32 + mt * 16 + g;
#pragma unroll
        for (int h = 0; h < 2; h++) {
            int row = rb + h * 8;
            if (row >= M) continue;
            float* crow = C + (size_t)row * HID;
#pragma unroll
            for (int nt = 0; nt < 10; nt++) {
                int col = nb0 + wn * 80 + nt * 8 + 2 * t;
                if (col >= 300) continue;           // drop pad cols (300..319)
                float x = acc[mt][nt][h * 2 + 0];
                float y = acc[mt][nt][h * 2 + 1];
                if (bias) { x += __ldg(bias + col); y += __ldg(bias + col + 1); }
                if (relu) { x = fmaxf(x, 0.f);      y = fmaxf(y, 0.f); }
                *reinterpret_cast<float2*>(crow + col) = make_float2(x, y);
            }
        }
    }
}

// ---------------- weight transpose + pad + tf32 round: Wt[n][k] = tf32(W[k][n]) ----------------
__global__ void transpose_pad(const float* __restrict__ W, float* __restrict__ Wt,
                              int K, int kpad)
{
    int i = blockIdx.x * blockDim.x + threadIdx.x;
    if (i >= 320 * kpad) return;
    int n = i / kpad, k = i - n * kpad;
    float v = (k < K && n < HID) ? W[(size_t)k * HID + n] : 0.f;
    Wt[i] = __uint_as_float(tf32c(v));
}

// ---------------- dst[row] = sum_j src[a2b[row][j]]  (float4) ----------------
__global__ void gather6(const float* __restrict__ src, const int* __restrict__ a2b,
                        float* __restrict__ dst, int total4)
{
    int i = blockIdx.x * blockDim.x + threadIdx.x;
    if (i >= total4) return;
    int row = i / 75, h = (i - row * 75) * 4;
    const int* nb = a2b + row * 6;
    float4 s = make_float4(0.f, 0.f, 0.f, 0.f);
#pragma unroll
    for (int j = 0; j < 6; j++) {
        int b = __ldg(nb + j);
        float4 v = __ldg(reinterpret_cast<const float4*>(src + (size_t)b * HID + h));
        s.x += v.x; s.y += v.y; s.z += v.z; s.w += v.w;
    }
    *reinterpret_cast<float4*>(dst + (size_t)row * HID + h) = s;
}

// ---------------- msg[b] = relu(inp[b] + aw[b2a[b]] - M[b2revb[b]]) ----------------
__global__ void combine_k(const float* __restrict__ inp, const float* __restrict__ aw,
                          const float* __restrict__ Mm, const int* __restrict__ b2a,
                          const int* __restrict__ b2revb, float* __restrict__ msg, int total4)
{
    int i = blockIdx.x * blockDim.x + threadIdx.x;
    if (i >= total4) return;
    int b = i / 75, h = (i - b * 75) * 4;
    int ia = __ldg(b2a + b);
    int ir = __ldg(b2revb + b);
    float4 vi = *reinterpret_cast<const float4*>(inp + (size_t)b * HID + h);
    float4 va = __ldg(reinterpret_cast<const float4*>(aw + (size_t)ia * HID + h));
    float4 vm = __ldg(reinterpret_cast<const float4*>(Mm + (size_t)ir * HID + h));
    float4 o;
    o.x = fmaxf(vi.x + va.x - vm.x, 0.f);
    o.y = fmaxf(vi.y + va.y - vm.y, 0.f);
    o.z = fmaxf(vi.z + va.z - vm.z, 0.f);
    o.w = fmaxf(vi.w + va.w - vm.w, 0.f);
    *reinterpret_cast<float4*>(msg + (size_t)b * HID + h) = o;
}

// ---------------- per-molecule mean (20 contiguous atoms, rows 20m+1..20m+20) ----------------
__global__ void mol_mean(const float* __restrict__ hidden, float* __restrict__ out)
{
    int i = blockIdx.x * blockDim.x + threadIdx.x;
    if (i >= N_MOLS_C * 75) return;
    int m = i / 75, h = (i - m * 75) * 4;
    const float* p = hidden + (size_t)(m * APM + 1) * HID + h;
    float4 s = make_float4(0.f, 0.f, 0.f, 0.f);
#pragma unroll
    for (int tt = 0; tt < APM; tt++) {
        float4 v = *reinterpret_cast<const float4*>(p + (size_t)tt * HID);
        s.x += v.x; s.y += v.y; s.z += v.z; s.w += v.w;
    }
    float4 o = make_float4(s.x * 0.05f, s.y * 0.05f, s.z * 0.05f, s.w * 0.05f);
    *reinterpret_cast<float4*>(out + (size_t)m * HID + h) = o;
}

// ---------------- launch ----------------
extern "C" void kernel_launch(void* const* d_in, const int* in_sizes, int n_in,
                              void* d_out, int out_size)
{
    const float* f_atoms = (const float*)d_in[0];
    const float* f_bonds = (const float*)d_in[1];
    const float* W_i     = (const float*)d_in[2];
    const float* W_h     = (const float*)d_in[3];
    const float* W_o     = (const float*)d_in[4];
    const float* b_o     = (const float*)d_in[5];
    const int*   a2b     = (const int*)d_in[6];
    const int*   b2a     = (const int*)d_in[7];
    const int*   b2revb  = (const int*)d_in[8];
    float* out = (float*)d_out;

    float *inp, *msg, *Mm, *aw, *hidden, *WtI, *WtH, *WtO;
    cudaGetSymbolAddress((void**)&inp,    g_inp);
    cudaGetSymbolAddress((void**)&msg,    g_msg);
    cudaGetSymbolAddress((void**)&Mm,     g_M);
    cudaGetSymbolAddress((void**)&aw,     g_aw);
    cudaGetSymbolAddress((void**)&hidden, g_hidden);
    cudaGetSymbolAddress((void**)&WtI,    g_WtI);
    cudaGetSymbolAddress((void**)&WtH,    g_WtH);
    cudaGetSymbolAddress((void**)&WtO,    g_WtO);

    cudaFuncSetAttribute(gemm_mma, cudaFuncAttributeMaxDynamicSharedMemorySize, SMEM_B);

    // 0) transpose + pad + tf32-round weights
    transpose_pad<<<(320 * 160 + 255) / 256, 256>>>(W_i, WtI, 147, 160);
    transpose_pad<<<(320 * 320 + 255) / 256, 256>>>(W_h, WtH, 300, 320);
    transpose_pad<<<(320 * 448 + 255) / 256, 256>>>(W_o, WtO, 433, 448);

    const dim3 gB((NB1 + 127) / 128, 2);
    const dim3 gA((NA1 + 127) / 128, 2);
    const int totB4 = NB1 * 75;
    const int totA4 = NA1 * 75;

    // 1) inp = relu(f_bonds @ W_i)
    gemm_mma<<<gB, 256, SMEM_B>>>(f_bonds, nullptr, WtI, nullptr, inp,
                                  NB1, 147, 160, 0, 1);

    // 2) two message-passing iterations:
    //    (a_msg[b2a] - msg[b2revb]) @ W_h == (sum_j M[a2b])[b2a] - M[b2revb], M = msg @ W_h
    const float* cur = inp;
    for (int d = 0; d < 2; d++) {
        gemm_mma<<<gB, 256, SMEM_B>>>(cur, nullptr, WtH, nullptr, Mm,
                                      NB1, 300, 320, 0, 0);
        gather6<<<(totA4 + 255) / 256, 256>>>(Mm, a2b, aw, totA4);
        combine_k<<<(totB4 + 255) / 256, 256>>>(inp, aw, Mm, b2a, b2revb, msg, totB4);
        cur = msg;
    }

    // 3) final per-atom aggregation
    gather6<<<(totA4 + 255) / 256, 256>>>(msg, a2b, aw, totA4);

    // 4) atom_hiddens = relu([f_atoms | aw] @ W_o + b_o), one fused K=433 GEMM
    gemm_mma<<<gA, 256, SMEM_B>>>(f_atoms, aw, WtO, b_o, hidden,
                                  NA1, 433, 448, 2, 1);

    // 5) per-molecule mean (counts are exactly 20 by construction)
    mol_mean<<<(N_MOLS_C * 75 + 255) / 256, 256>>>(hidden, out);
}

// round 17
// speedup vs baseline: 3.1441x; 3.1441x over previous
#include <cuda_runtime.h>

// ---------------- problem constants ----------------
#define HID        300
#define N_ATOMS_C  100000
#define N_BONDS_C  200000
#define NA1        (N_ATOMS_C + 1)
#define NB1        (N_BONDS_C + 1)
#define N_MOLS_C   5000
#define APM        20

// ---------------- scratch (static __device__, allocation-free) ----------------
// +64 float tails: W_h GEMM reads rows with stride 300 out to kpad=320; tails stay
// zero-initialized (never written) so stray tail reads are finite and hit B's zero pad.
__device__ float g_inp[NB1 * HID + 64];
__device__ float g_msg[NB1 * HID + 64];
__device__ float g_M[NB1 * HID];
__device__ float g_aw[NA1 * HID];
__device__ float g_hidden[NA1 * HID];
__device__ float g_fb[NB1 * 160];      // f_bonds padded 147->160, tf32-rounded
__device__ float g_cat[(size_t)NA1 * 448]; // [f_atoms(133)|aw(300)|0] padded, tf32-rounded
// fragment-shuffled weights: [half][chunk][slice][n8tile][lane][pair]
__device__ float g_WtI[320 * 160];
__device__ float g_WtH[320 * 320];
__device__ float g_WtO[320 * 448];

// ---------------- helpers ----------------
__device__ __forceinline__ unsigned tf32c(float x) {
    unsigned r;
    asm("cvt.rna.tf32.f32 %0, %1;" : "=r"(r) : "f"(x));
    return r;
}
__device__ __forceinline__ float tf32f(float x) { return __uint_as_float(tf32c(x)); }

__device__ __forceinline__ unsigned smem_u32(const void* p) {
    unsigned r;
    asm("{ .reg .u64 t; cvta.to.shared.u64 t, %1; cvt.u32.u64 %0, t; }" : "=r"(r) : "l"(p));
    return r;
}
__device__ __forceinline__ void mma8(float d[4], uint4 a, uint2 b) {
    asm volatile(
        "mma.sync.aligned.m16n8k8.row.col.f32.tf32.tf32.f32 "
        "{%0,%1,%2,%3}, {%4,%5,%6,%7}, {%8,%9}, {%0,%1,%2,%3};"
        : "+f"(d[0]), "+f"(d[1]), "+f"(d[2]), "+f"(d[3])
        : "r"(a.x), "r"(a.y), "r"(a.z), "r"(a.w), "r"(b.x), "r"(b.y));
}
__device__ __forceinline__ void cpa16(unsigned dst, const float* src, int sz) {
    asm volatile("cp.async.ca.shared.global [%0], [%1], 16, %2;"
                 :: "r"(dst), "l"(src), "r"(sz));
}
#define CP_COMMIT() asm volatile("cp.async.commit_group;")
#define CP_WAIT1()  asm volatile("cp.async.wait_group 1;")

// ---------------- mma.sync tf32 GEMM ----------------
// C[M x 300] = act(A[M x kpad] @ WtF + bias)
// A: row-major, row stride lda (rows 16B-aligned), values pre-tf32-rounded;
//    columns [K, kpad) contribute zero because WtF is zero there.
// WtF: fragment-major shuffled weights (see transpose_pad).
// CTA: 128 rows x 160 cols (blockIdx.y in {0,1}); BK=32; 512 thr = 16 warps (4m x 4n);
// warp tile 32x40. 3-stage cp.async pipeline, 1 bar/chunk.
#define A_ROWP   36                    // 32 + 4 pad: bank = (4r+c)%32, conflict-free
#define A_FL     (128 * A_ROWP)        // 4608 floats / stage
#define B_FL     5120                  // 160 x 32 / stage, fragment-major
#define STAGE_FL (A_FL + B_FL)         // 9728 floats
#define SMEM_BYT (3 * STAGE_FL * 4)    // 116736 B

__global__ __launch_bounds__(512, 1)
void gemm_mma(const float* __restrict__ A, int lda,
              const float* __restrict__ WtF, const float* __restrict__ bias,
              float* __restrict__ C, int M, int kpad, int relu, int oround)
{
    extern __shared__ float sm[];
    const int tid  = threadIdx.x;
    const int warp = tid >> 5, lane = tid & 31;
    const int g    = lane >> 2, t = lane & 3;
    const int wm   = warp & 3,  wn = warp >> 2;
    const int bm   = blockIdx.x * 128;
    const int nb0  = blockIdx.y * 160;
    const int nCh  = kpad >> 5;
    const int half = blockIdx.y;

    float acc[2][5][4];
#pragma unroll
    for (int mt = 0; mt < 2; mt++)
#pragma unroll
        for (int nt = 0; nt < 5; nt++)
#pragma unroll
            for (int j = 0; j < 4; j++) acc[mt][nt][j] = 0.f;

    // staging indices
    const int ar  = tid >> 3;          // row 0..63 (+64 for i=1)
    const int seg = tid & 7;           // 16B segment within 32-float row

    auto issue = [&](int ch) {
        float* st = sm + (ch % 3) * STAGE_FL;
        const int k0 = ch << 5;
        // A: 128 rows x 128B, 1024 ops, 2/thread
#pragma unroll
        for (int i = 0; i < 2; i++) {
            int r  = ar + i * 64;
            int gr = bm + r;
            unsigned dst = smem_u32(st + r * A_ROWP + seg * 4);
            const float* src = A + (size_t)gr * lda + k0 + seg * 4;
            cpa16(dst, src, (gr < M) ? 16 : 0);
        }
        // B: contiguous 5120 floats from fragment-shuffled gmem
        const float* bsrc = WtF + (size_t)(half * nCh + ch) * B_FL;
        float* bdst = st + A_FL;
#pragma unroll
        for (int i = 0; i < 3; i++) {
            int q = tid + i * 512;
            if (q < 1280) cpa16(smem_u32(bdst + q * 4), bsrc + q * 4, 16);
        }
    };

    issue(0); CP_COMMIT();
    issue(1); CP_COMMIT();

    for (int ch = 0; ch < nCh; ch++) {
        CP_WAIT1();
        __syncthreads();
        if (ch + 2 < nCh) issue(ch + 2);
        CP_COMMIT();

        const float* As = sm + (ch % 3) * STAGE_FL;
        const float* Bs = As + A_FL;
#pragma unroll
        for (int s = 0; s < 4; s++) {
            uint4 af[2];
#pragma unroll
            for (int mt = 0; mt < 2; mt++) {
                const float* ap = As + (wm * 32 + mt * 16 + g) * A_ROWP + s * 8 + t;
                af[mt].x = __float_as_uint(ap[0]);
                af[mt].y = __float_as_uint(ap[8 * A_ROWP]);
                af[mt].z = __float_as_uint(ap[4]);
                af[mt].w = __float_as_uint(ap[8 * A_ROWP + 4]);
            }
            uint2 bf[5];
#pragma unroll
            for (int nt = 0; nt < 5; nt++)
                bf[nt] = *reinterpret_cast<const uint2*>(
                    Bs + s * 1280 + (wn * 5 + nt) * 64 + lane * 2);
#pragma unroll
            for (int mt = 0; mt < 2; mt++)
#pragma unroll
                for (int nt = 0; nt < 5; nt++)
                    mma8(acc[mt][nt], af[mt], bf[nt]);
        }
        __syncthreads();
    }

    // epilogue: c0,c1 = (row g, cols 2t,2t+1); c2,c3 = (row g+8, same cols)
#pragma unroll
    for (int mt = 0; mt < 2; mt++) {
        int rb = bm + wm * 32 + mt * 16 + g;
#pragma unroll
        for (int h = 0; h < 2; h++) {
            int row = rb + h * 8;
            if (row >= M) continue;
            float* crow = C + (size_t)row * HID;
#pragma unroll
            for (int nt = 0; nt < 5; nt++) {
                int col = nb0 + wn * 40 + nt * 8 + 2 * t;
                if (col >= 300) continue;
                float x = acc[mt][nt][h * 2 + 0];
                float y = acc[mt][nt][h * 2 + 1];
                if (bias)  { x += __ldg(bias + col); y += __ldg(bias + col + 1); }
                if (relu)  { x = fmaxf(x, 0.f);      y = fmaxf(y, 0.f); }
                if (oround){ x = tf32f(x);           y = tf32f(y); }
                *reinterpret_cast<float2*>(crow + col) = make_float2(x, y);
            }
        }
    }
}

// ---------------- weight shuffle: W[K x 300] -> fragment-major WtF, tf32, zero-padded ----
__global__ void transpose_pad(const float* __restrict__ W, float* __restrict__ Wt,
                              int K, int kpad)
{
    int i = blockIdx.x * blockDim.x + threadIdx.x;
    if (i >= 320 * kpad) return;
    const int nCh = kpad >> 5;
    int u = i;
    int p  = u & 1;  u >>= 1;
    int l  = u & 31; u >>= 5;
    int nt = u % 20; u /= 20;
    int sl = u & 3;  u >>= 2;
    int c  = u % nCh;
    int h  = u / nCh;
    int gg = l >> 2, tt = l & 3;
    int n = h * 160 + nt * 8 + gg;
    int k = c * 32 + sl * 8 + tt + p * 4;
    float v = (k < K && n < HID) ? W[(size_t)k * HID + n] : 0.f;
    Wt[i] = tf32f(v);
}

// ---------------- f_bonds pad 147->160 + tf32 round ----------------
__global__ void prep_fb(const float* __restrict__ fb, float* __restrict__ out)
{
    int i = blockIdx.x * blockDim.x + threadIdx.x;
    if (i >= NB1 * 160) return;
    int r = i / 160, k = i - r * 160;
    out[i] = (k < 147) ? tf32f(fb[(size_t)r * 147 + k]) : 0.f;
}

// ---------------- concat [f_atoms|aw|0] -> 448, tf32 round ----------------
__global__ void prep_cat(const float* __restrict__ fa, const float* __restrict__ aw,
                         float* __restrict__ out)
{
    size_t i = (size_t)blockIdx.x * blockDim.x + threadIdx.x;
    if (i >= (size_t)NA1 * 448) return;
    int r = (int)(i / 448), k = (int)(i - (size_t)r * 448);
    float v = 0.f;
    if (k < 133)      v = fa[(size_t)r * 133 + k];
    else if (k < 433) v = aw[(size_t)r * 300 + (k - 133)];
    out[i] = tf32f(v);
}

// ---------------- dst[row] = sum_j src[a2b[row][j]]  (float4) ----------------
__global__ void gather6(const float* __restrict__ src, const int* __restrict__ a2b,
                        float* __restrict__ dst, int total4)
{
    int i = blockIdx.x * blockDim.x + threadIdx.x;
    if (i >= total4) return;
    int row = i / 75, h = (i - row * 75) * 4;
    const int* nb = a2b + row * 6;
    float4 s = make_float4(0.f, 0.f, 0.f, 0.f);
#pragma unroll
    for (int j = 0; j < 6; j++) {
        int b = __ldg(nb + j);
        float4 v = __ldg(reinterpret_cast<const float4*>(src + (size_t)b * HID + h));
        s.x += v.x; s.y += v.y; s.z += v.z; s.w += v.w;
    }
    *reinterpret_cast<float4*>(dst + (size_t)row * HID + h) = s;
}

// ---------------- msg[b] = tf32(relu(inp[b] + aw[b2a[b]] - M[b2revb[b]])) ----------------
__global__ void combine_k(const float* __restrict__ inp, const float* __restrict__ aw,
                          const float* __restrict__ Mm, const int* __restrict__ b2a,
                          const int* __restrict__ b2revb, float* __restrict__ msg, int total4)
{
    int i = blockIdx.x * blockDim.x + threadIdx.x;
    if (i >= total4) return;
    int b = i / 75, h = (i - b * 75) * 4;
    int ia = __ldg(b2a + b);
    int ir = __ldg(b2revb + b);
    float4 vi = *reinterpret_cast<const float4*>(inp + (size_t)b * HID + h);
    float4 va = __ldg(reinterpret_cast<const float4*>(aw + (size_t)ia * HID + h));
    float4 vm = __ldg(reinterpret_cast<const float4*>(Mm + (size_t)ir * HID + h));
    float4 o;
    o.x = tf32f(fmaxf(vi.x + va.x - vm.x, 0.f));
    o.y = tf32f(fmaxf(vi.y + va.y - vm.y, 0.f));
    o.z = tf32f(fmaxf(vi.z + va.z - vm.z, 0.f));
    o.w = tf32f(fmaxf(vi.w + va.w - vm.w, 0.f));
    *reinterpret_cast<float4*>(msg + (size_t)b * HID + h) = o;
}

// ---------------- per-molecule mean (20 contiguous atoms, rows 20m+1..20m+20) ----------------
__global__ void mol_mean(const float* __restrict__ hidden, float* __restrict__ out)
{
    int i = blockIdx.x * blockDim.x + threadIdx.x;
    if (i >= N_MOLS_C * 75) return;
    int m = i / 75, h = (i - m * 75) * 4;
    const float* p = hidden + (size_t)(m * APM + 1) * HID + h;
    float4 s = make_float4(0.f, 0.f, 0.f, 0.f);
#pragma unroll
    for (int tt = 0; tt < APM; tt++) {
        float4 v = *reinterpret_cast<const float4*>(p + (size_t)tt * HID);
        s.x += v.x; s.y += v.y; s.z += v.z; s.w += v.w;
    }
    float4 o = make_float4(s.x * 0.05f, s.y * 0.05f, s.z * 0.05f, s.w * 0.05f);
    *reinterpret_cast<float4*>(out + (size_t)m * HID + h) = o;
}

// ---------------- launch ----------------
extern "C" void kernel_launch(void* const* d_in, const int* in_sizes, int n_in,
                              void* d_out, int out_size)
{
    const float* f_atoms = (const float*)d_in[0];
    const float* f_bonds = (const float*)d_in[1];
    const float* W_i     = (const float*)d_in[2];
    const float* W_h     = (const float*)d_in[3];
    const float* W_o     = (const float*)d_in[4];
    const float* b_o     = (const float*)d_in[5];
    const int*   a2b     = (const int*)d_in[6];
    const int*   b2a     = (const int*)d_in[7];
    const int*   b2revb  = (const int*)d_in[8];
    float* out = (float*)d_out;

    float *inp, *msg, *Mm, *aw, *hidden, *fb, *cat, *WtI, *WtH, *WtO;
    cudaGetSymbolAddress((void**)&inp,    g_inp);
    cudaGetSymbolAddress((void**)&msg,    g_msg);
    cudaGetSymbolAddress((void**)&Mm,     g_M);
    cudaGetSymbolAddress((void**)&aw,     g_aw);
    cudaGetSymbolAddress((void**)&hidden, g_hidden);
    cudaGetSymbolAddress((void**)&fb,     g_fb);
    cudaGetSymbolAddress((void**)&cat,    g_cat);
    cudaGetSymbolAddress((void**)&WtI,    g_WtI);
    cudaGetSymbolAddress((void**)&WtH,    g_WtH);
    cudaGetSymbolAddress((void**)&WtO,    g_WtO);

    cudaFuncSetAttribute(gemm_mma, cudaFuncAttributeMaxDynamicSharedMemorySize, SMEM_BYT);

    // 0) weight shuffle + input prepad
    transpose_pad<<<(320 * 160 + 255) / 256, 256>>>(W_i, WtI, 147, 160);
    transpose_pad<<<(320 * 320 + 255) / 256, 256>>>(W_h, WtH, 300, 320);
    transpose_pad<<<(320 * 448 + 255) / 256, 256>>>(W_o, WtO, 433, 448);
    prep_fb<<<(NB1 * 160 + 255) / 256, 256>>>(f_bonds, fb);

    const dim3 gB((NB1 + 127) / 128, 2);
    const dim3 gA((NA1 + 127) / 128, 2);
    const int totB4 = NB1 * 75;
    const int totA4 = NA1 * 75;

    // 1) inp = tf32(relu(f_bonds @ W_i))
    gemm_mma<<<gB, 512, SMEM_BYT>>>(fb, 160, WtI, nullptr, inp, NB1, 160, 1, 1);

    // 2) two message-passing iterations:
    //    (a_msg[b2a] - msg[b2revb]) @ W_h == (sum_j M[a2b])[b2a] - M[b2revb], M = msg @ W_h
    const float* cur = inp;
    for (int d = 0; d < 2; d++) {
        gemm_mma<<<gB, 512, SMEM_BYT>>>(cur, 300, WtH, nullptr, Mm, NB1, 320, 0, 0);
        gather6<<<(totA4 + 255) / 256, 256>>>(Mm, a2b, aw, totA4);
        combine_k<<<(totB4 + 255) / 256, 256>>>(inp, aw, Mm, b2a, b2revb, msg, totB4);
        cur = msg;
    }

    // 3) final per-atom aggregation + concat build
    gather6<<<(totA4 + 255) / 256, 256>>>(msg, a2b, aw, totA4);
    prep_cat<<<(int)(((size_t)NA1 * 448 + 255) / 256), 256>>>(f_atoms, aw, cat);

    // 4) atom_hiddens = relu([f_atoms|aw] @ W_o + b_o)
    gemm_mma<<<gA, 512, SMEM_BYT>>>(cat, 448, WtO, b_o, hidden, NA1, 448, 1, 0);

    // 5) per-molecule mean (counts are exactly 20 by construction)
    mol_mean<<<(N_MOLS_C * 75 + 255) / 256, 256>>>(hidden, out);
}